// round 2
// baseline (speedup 1.0000x reference)
#include <cuda_runtime.h>
#include <cuda_bf16.h>
#include <math.h>

// Problem dims
#define BB 4
#define SS 1024
#define DM 1024
#define NH 16
#define DK 64
#define DV 64

// Scratch for projected Q/K/V in [b, h, s, d] layout
__device__ float g_Q[BB * NH * SS * DK];
__device__ float g_K[BB * NH * SS * DK];
__device__ float g_V[BB * NH * SS * DV];

// ---------------------------------------------------------------------------
// Projection GEMM: Y = X @ W + b, remapped to [b, h, s, d]
// X: [4096, 1024], W: [1024, 1024]. 128x128x8 tiles, 8x8 per thread.
// gridDim.z selects q / k / v.
// ---------------------------------------------------------------------------
#define PBM 128
#define PBN 128
#define PBK 8

__global__ __launch_bounds__(256) void proj_kernel(
    const float* __restrict__ xq, const float* __restrict__ xk, const float* __restrict__ xv,
    const float* __restrict__ wq, const float* __restrict__ wk, const float* __restrict__ wv,
    const float* __restrict__ bq, const float* __restrict__ bk, const float* __restrict__ bv)
{
    __shared__ float As[PBK][PBM];
    __shared__ float Bs[PBK][PBN];

    const float* X; const float* W; const float* bias; float* out;
    int which = blockIdx.z;
    if (which == 0)      { X = xq; W = wq; bias = bq; out = g_Q; }
    else if (which == 1) { X = xk; W = wk; bias = bk; out = g_K; }
    else                 { X = xv; W = wv; bias = bv; out = g_V; }

    const int tid = threadIdx.x;
    const int tileM = blockIdx.y * PBM;
    const int tileN = blockIdx.x * PBN;

    const int ty = tid >> 4;          // 0..15
    const int tx = tid & 15;          // 0..15

    const int arow = tid >> 1;        // 0..127
    const int acol = (tid & 1) * 4;   // 0 or 4
    const int brow = tid >> 5;        // 0..7
    const int bcol = (tid & 31) * 4;  // 0..124

    float acc[8][8];
#pragma unroll
    for (int i = 0; i < 8; i++)
#pragma unroll
        for (int j = 0; j < 8; j++) acc[i][j] = 0.0f;

    for (int k0 = 0; k0 < DM; k0 += PBK) {
        float4 av = *(const float4*)&X[(size_t)(tileM + arow) * DM + k0 + acol];
        float4 bv4 = *(const float4*)&W[(size_t)(k0 + brow) * DM + tileN + bcol];
        __syncthreads();
        As[acol + 0][arow] = av.x;
        As[acol + 1][arow] = av.y;
        As[acol + 2][arow] = av.z;
        As[acol + 3][arow] = av.w;
        *(float4*)&Bs[brow][bcol] = bv4;
        __syncthreads();
#pragma unroll
        for (int kk = 0; kk < PBK; kk++) {
            float4 a0 = *(const float4*)&As[kk][ty * 8];
            float4 a1 = *(const float4*)&As[kk][ty * 8 + 4];
            float4 b0 = *(const float4*)&Bs[kk][tx * 8];
            float4 b1 = *(const float4*)&Bs[kk][tx * 8 + 4];
            float a[8] = {a0.x, a0.y, a0.z, a0.w, a1.x, a1.y, a1.z, a1.w};
            float b[8] = {b0.x, b0.y, b0.z, b0.w, b1.x, b1.y, b1.z, b1.w};
#pragma unroll
            for (int i = 0; i < 8; i++)
#pragma unroll
                for (int j = 0; j < 8; j++) acc[i][j] += a[i] * b[j];
        }
    }

    // Epilogue: bias add + remap to [b, h, s, d]
#pragma unroll
    for (int i = 0; i < 8; i++) {
        int r = tileM + ty * 8 + i;
        int bb = r >> 10;
        int s = r & (SS - 1);
#pragma unroll
        for (int j4 = 0; j4 < 2; j4++) {
            int c = tileN + tx * 8 + j4 * 4;
            int h = c >> 6;
            int d = c & 63;
            float4 o;
            o.x = acc[i][j4 * 4 + 0] + bias[c + 0];
            o.y = acc[i][j4 * 4 + 1] + bias[c + 1];
            o.z = acc[i][j4 * 4 + 2] + bias[c + 2];
            o.w = acc[i][j4 * 4 + 3] + bias[c + 3];
            *(float4*)&out[(((size_t)(bb * NH + h) * SS + s) << 6) + d] = o;
        }
    }
}

// ---------------------------------------------------------------------------
// Fused attention: per block = (b, h, 32 q-rows).
// Full 1024-wide score row kept in smem -> one-pass softmax -> write attn to
// gmem fused -> PV directly from smem (attn never re-read from HBM).
// smem strides padded odd => conflict-free broadcast/multicast LDS.
// ---------------------------------------------------------------------------
#define QT 32
#define KT 128
#define SQP 65
#define SKP 65
#define SSP 1025
#define ATTN_SMEM_FLOATS (QT * SQP + KT * SKP + QT * SSP)
#define ATTN_SMEM_BYTES (ATTN_SMEM_FLOATS * 4)

__global__ __launch_bounds__(256) void attn_kernel(
    float* __restrict__ ctx_out, float* __restrict__ attn_out)
{
    extern __shared__ float sm[];
    float* sQ = sm;                  // QT  x SQP
    float* sKV = sQ + QT * SQP;      // KT  x SKP
    float* sS = sKV + KT * SKP;      // QT  x SSP

    const int tid = threadIdx.x;
    const int qt = blockIdx.x;       // 0..31
    const int h = blockIdx.y;        // 0..15
    const int b = blockIdx.z;        // 0..3

    const float* Qbase = g_Q + ((size_t)(b * NH + h) * SS + qt * QT) * DK;
    const float* Kbase = g_K + (size_t)(b * NH + h) * SS * DK;
    const float* Vbase = g_V + (size_t)(b * NH + h) * SS * DV;

    // Load Q tile (32 x 64)
    for (int f = tid; f < QT * 16; f += 256) {
        int row = f >> 4;
        int dq = (f & 15) * 4;
        float4 v = *(const float4*)&Qbase[row * DK + dq];
        sQ[row * SQP + dq + 0] = v.x;
        sQ[row * SQP + dq + 1] = v.y;
        sQ[row * SQP + dq + 2] = v.z;
        sQ[row * SQP + dq + 3] = v.w;
    }

    const int qi0 = (tid & 7) * 4;   // 8 groups of 4 q-rows
    const int kj0 = (tid >> 3) * 4;  // 32 groups of 4 k-cols

    // ---- Scores: S = (Q K^T) / 8, tile over K ----
    for (int kt = 0; kt < SS / KT; kt++) {
        __syncthreads();
        for (int f = tid; f < KT * 16; f += 256) {
            int row = f >> 4;
            int dq = (f & 15) * 4;
            float4 v = *(const float4*)&Kbase[(kt * KT + row) * DK + dq];
            sKV[row * SKP + dq + 0] = v.x;
            sKV[row * SKP + dq + 1] = v.y;
            sKV[row * SKP + dq + 2] = v.z;
            sKV[row * SKP + dq + 3] = v.w;
        }
        __syncthreads();

        float acc[4][4];
#pragma unroll
        for (int i = 0; i < 4; i++)
#pragma unroll
            for (int j = 0; j < 4; j++) acc[i][j] = 0.0f;

#pragma unroll 8
        for (int d = 0; d < DK; d++) {
            float a[4], bb[4];
#pragma unroll
            for (int i = 0; i < 4; i++) a[i] = sQ[(qi0 + i) * SQP + d];
#pragma unroll
            for (int j = 0; j < 4; j++) bb[j] = sKV[(kj0 + j) * SKP + d];
#pragma unroll
            for (int i = 0; i < 4; i++)
#pragma unroll
                for (int j = 0; j < 4; j++) acc[i][j] += a[i] * bb[j];
        }
#pragma unroll
        for (int i = 0; i < 4; i++)
#pragma unroll
            for (int j = 0; j < 4; j++)
                sS[(qi0 + i) * SSP + kt * KT + kj0 + j] = acc[i][j] * 0.125f;
    }
    __syncthreads();

    // ---- Softmax per row (warp handles 4 rows) + fused attn write ----
    const int warp = tid >> 5;
    const int lane = tid & 31;
    for (int rr = 0; rr < 4; rr++) {
        int r = warp * 4 + rr;
        float* row = sS + r * SSP;
        float mx = -3.0e38f;
        for (int c = lane; c < SS; c += 32) mx = fmaxf(mx, row[c]);
#pragma unroll
        for (int o = 16; o > 0; o >>= 1) mx = fmaxf(mx, __shfl_xor_sync(0xffffffffu, mx, o));
        float sum = 0.0f;
        for (int c = lane; c < SS; c += 32) {
            float e = __expf(row[c] - mx);
            row[c] = e;
            sum += e;
        }
#pragma unroll
        for (int o = 16; o > 0; o >>= 1) sum += __shfl_xor_sync(0xffffffffu, sum, o);
        float inv = 1.0f / sum;
        float* arow = attn_out + ((size_t)(b * NH + h) * SS + qt * QT + r) * SS;
        for (int c = lane; c < SS; c += 32) {
            float p = row[c] * inv;
            row[c] = p;
            arow[c] = p;
        }
    }

    // ---- PV: context = P @ V, V tiled through sKV ----
    const int d0 = (tid >> 3) * 2;   // 32 groups of 2 d-cols
    float acc2[4][2];
#pragma unroll
    for (int i = 0; i < 4; i++) { acc2[i][0] = 0.0f; acc2[i][1] = 0.0f; }

    for (int vt = 0; vt < SS / KT; vt++) {
        __syncthreads();
        for (int f = tid; f < KT * 16; f += 256) {
            int row = f >> 4;
            int dq = (f & 15) * 4;
            float4 v = *(const float4*)&Vbase[(vt * KT + row) * DV + dq];
            sKV[row * SKP + dq + 0] = v.x;
            sKV[row * SKP + dq + 1] = v.y;
            sKV[row * SKP + dq + 2] = v.z;
            sKV[row * SKP + dq + 3] = v.w;
        }
        __syncthreads();
#pragma unroll 8
        for (int kkl = 0; kkl < KT; kkl++) {
            int kk = vt * KT + kkl;
            float p[4], vv[2];
#pragma unroll
            for (int i = 0; i < 4; i++) p[i] = sS[(qi0 + i) * SSP + kk];
            vv[0] = sKV[kkl * SKP + d0 + 0];
            vv[1] = sKV[kkl * SKP + d0 + 1];
#pragma unroll
            for (int i = 0; i < 4; i++) {
                acc2[i][0] += p[i] * vv[0];
                acc2[i][1] += p[i] * vv[1];
            }
        }
    }

    // Write context in [b, s, h*64 + d]
#pragma unroll
    for (int i = 0; i < 4; i++) {
        int q = qt * QT + qi0 + i;
        float* crow = ctx_out + ((size_t)b * SS + q) * (NH * DV) + h * DV + d0;
        crow[0] = acc2[i][0];
        crow[1] = acc2[i][1];
    }
}

// ---------------------------------------------------------------------------
// Launch
// ---------------------------------------------------------------------------
extern "C" void kernel_launch(void* const* d_in, const int* in_sizes, int n_in,
                              void* d_out, int out_size)
{
    const float* q  = (const float*)d_in[0];
    const float* k  = (const float*)d_in[1];
    const float* v  = (const float*)d_in[2];
    const float* wq = (const float*)d_in[3];
    const float* wk = (const float*)d_in[4];
    const float* wv = (const float*)d_in[5];
    const float* bq = (const float*)d_in[6];
    const float* bk = (const float*)d_in[7];
    const float* bv = (const float*)d_in[8];
    // d_in[9] = attn_mask (falsy scalar) -> no masking

    float* ctx  = (float*)d_out;
    float* attn = (float*)d_out + (size_t)BB * SS * NH * DV;

    // Opt-in smem for the attention kernel (non-stream API; legal during
    // graph capture). Tolerate repeated calls.
    (void)cudaFuncSetAttribute(attn_kernel,
                               cudaFuncAttributeMaxDynamicSharedMemorySize,
                               ATTN_SMEM_BYTES);

    dim3 pgrid(DM / PBN, (BB * SS) / PBM, 3);
    proj_kernel<<<pgrid, 256>>>(q, k, v, wq, wk, wv, bq, bk, bv);

    dim3 agrid(SS / QT, NH, BB);
    attn_kernel<<<agrid, 256, ATTN_SMEM_BYTES>>>(ctx, attn);
}